// round 10
// baseline (speedup 1.0000x reference)
#include <cuda_runtime.h>
#include <math.h>

// ScatTransform1D via implicit GEMM on fallback HMMA (mma.sync.m16n8k16.bf16),
// bf16 hi/lo split for fp32-grade accuracy (keep xh*fh + xl*fh + xh*fl).
//
// Round 9: software-pipelined. B chunks double-buffered into smem via
// cp.async.cg one chunk ahead (MMA reads become LDS.128, no long-scoreboard);
// x window prefetched into registers one chunk ahead; whl convert double-
// buffered; 2 syncs/chunk. prep_bank reads coalesced via smem staging.

#define KFILT 192
#define QSTEP 16
#define NBATCH 2
#define NOCT 12
#define MT_M 128
#define KC 64
#define CHUNK_WORDS 2048           // (2 split)(4 kk)(2 rr)(32 lane)(4 c) words
#define MAX_CHUNKS_TOTAL 1600      // sum over octaves of nc_j (=1477 actual)

typedef unsigned long long ull;

__device__ __align__(16) unsigned g_bank[MAX_CHUNKS_TOTAL * CHUNK_WORDS]; // 13MB

static __device__ __forceinline__ unsigned bfpair(float lo, float hi) {
    unsigned r;   // lower 16 bits <- lo (tap k), upper <- hi (tap k+1)
    asm("cvt.rn.bf16x2.f32 %0, %1, %2;" : "=r"(r) : "f"(hi), "f"(lo));
    return r;
}

// Octave support params; MUST be identical in prep + main kernels.
static __device__ __forceinline__ int oct_params(int j, int P, int* lo, int* nc) {
    int off = 0;
    for (int jj = 0; jj <= j; jj++) {
        int M = (int)ceil(6.0 * exp2((double)jj + 0.9375)) + 2;  // max-q support
        if (M > P) M = P;
        int c = (2 * M + KC) / KC;      // ceil((2M+1)/64)
        if (jj < j) off += c;
        else { *lo = P - M; *nc = c; }
    }
    return off * CHUNK_WORDS;
}

// ---------------------------------------------------------------- prep kernel
// Same word layout as before:
// word index = ((((sp*4 + kk)*2 + rr)*32 + lane)*4 + c)
//   n = c*8 + (lane>>2); tap k = kk*16 + rr*8 + (lane&3)*2; d = lo + ci*64 + k
// Coalesced: stage the 32x64 tap block in smem (contiguous row reads), then
// emit words in wd order (coalesced writes) from smem.
__global__ void prep_bank(const float* __restrict__ fr, const float* __restrict__ fi,
                          int L, int P)
{
    __shared__ float fsm[32][66];
    const int j = blockIdx.y;
    int lo, nc;
    const int off = oct_params(j, P, &lo, &nc);
    const int ci = blockIdx.x;
    if (ci >= nc) return;
    const int d0 = lo + ci * KC;

    // Stage: thread (n = tid>>3) reads 8 consecutive taps at kb = (tid&7)*8.
    {
        const int n  = threadIdx.x >> 3;
        const int kb = (threadIdx.x & 7) * 8;
        const float* src = ((n & 1) ? fi : fr) + (size_t)(j * QSTEP + (n >> 1)) * L;
        #pragma unroll
        for (int u = 0; u < 8; u++) {
            const int d = d0 + kb + u;
            fsm[n][kb + u] = (d < L) ? __ldg(src + d) : 0.0f;
        }
    }
    __syncthreads();

    unsigned* dst = g_bank + off + ci * CHUNK_WORDS;
    for (int wd = threadIdx.x; wd < CHUNK_WORDS; wd += blockDim.x) {
        const int c    = wd & 3;
        const int lane = (wd >> 2) & 31;
        const int rr   = (wd >> 7) & 1;
        const int kk   = (wd >> 8) & 3;
        const int sp   = (wd >> 10) & 1;
        const int n    = c * 8 + (lane >> 2);
        const int k    = kk * 16 + rr * 8 + (lane & 3) * 2;
        const float f0 = fsm[n][k], f1 = fsm[n][k + 1];
        const unsigned ph = bfpair(f0, f1);
        if (sp == 0) {
            dst[wd] = ph;
        } else {
            const float h0 = __uint_as_float(ph << 16);
            const float h1 = __uint_as_float(ph & 0xFFFF0000u);
            dst[wd] = bfpair(f0 - h0, f1 - h1);
        }
    }
}

// ---------------------------------------------------------------- main kernel
static __device__ __forceinline__ void mma_bf16(float c[4],
                                                unsigned a0, unsigned a1,
                                                unsigned a2, unsigned a3,
                                                unsigned b0, unsigned b1)
{
    asm volatile(
        "mma.sync.aligned.m16n8k16.row.col.f32.bf16.bf16.f32 "
        "{%0,%1,%2,%3}, {%4,%5,%6,%7}, {%8,%9}, {%0,%1,%2,%3};"
        : "+f"(c[0]), "+f"(c[1]), "+f"(c[2]), "+f"(c[3])
        : "r"(a0), "r"(a1), "r"(a2), "r"(a3), "r"(b0), "r"(b1));
}

static __device__ __forceinline__ void cpasync16(void* sdst, const void* gsrc) {
    const unsigned s = (unsigned)__cvta_generic_to_shared(sdst);
    asm volatile("cp.async.cg.shared.global [%0], [%1], 16;"
                 :: "r"(s), "l"(gsrc) : "memory");
}

__global__ __launch_bounds__(128)
void scat_mma_kernel(const float* __restrict__ x, float* __restrict__ out,
                     int T, int L, int P)
{
    __shared__ float wbuf[200];
    __shared__ ull   whl[2][192];                        // (hi-pair, lo-pair)
    __shared__ __align__(16) unsigned bbuf[2][CHUNK_WORDS];

    const int tid  = threadIdx.x;
    const int wix  = tid >> 5;
    const int lane = tid & 31;
    const int t0   = blockIdx.x * MT_M;
    const int j    = (NOCT - 1) - blockIdx.y;            // heavy octaves first
    const int b    = blockIdx.z;

    int lo, nc;
    const int off = oct_params(j, P, &lo, &nc);
    const float* xb = x + (size_t)b * T;
    const unsigned* gb = g_bank + off;

    float acc[2][4][4];
    #pragma unroll
    for (int mt = 0; mt < 2; mt++)
        #pragma unroll
        for (int c = 0; c < 4; c++)
            #pragma unroll
            for (int r = 0; r < 4; r++) acc[mt][c][r] = 0.0f;

    // A-fragment base smem index: m + k with m = wix*32 + (lane>>2),
    // k = 2*(lane&3); (+8 row) and (+8 col) coincide for Toeplitz A.
    const int abase = wix * 32 + (lane >> 2) + (lane & 3) * 2;

    // ---- pipeline prologue: B chunk 0 via cp.async, x window 0 into regs.
    float xr0, xr1;
    {
        const unsigned* src = gb + tid * 4;
        #pragma unroll
        for (int r = 0; r < 4; r++)
            cpasync16(&bbuf[0][tid * 4 + r * 512], src + r * 512);
        asm volatile("cp.async.commit_group;" ::: "memory");
        const int g0 = t0 + lo - P;
        const int ga = g0 + tid, gv = g0 + 128 + tid;
        xr0 = (ga >= 0 && ga < T) ? __ldg(xb + ga) : 0.0f;
        xr1 = (tid < 66 && gv >= 0 && gv < T) ? __ldg(xb + gv) : 0.0f;
    }

    for (int ci = 0; ci < nc; ci++) {
        const int cur = ci & 1, nxt = cur ^ 1;
        const int cn  = (ci + 1 < nc) ? ci + 1 : nc - 1;   // clamp (redundant tail)

        wbuf[tid] = xr0;
        if (tid < 66) wbuf[128 + tid] = xr1;
        __syncthreads();

        // Convert window -> packed (hi, lo) bf16 pairs.
        for (int i = tid; i < 192; i += 128) {
            const float x0 = wbuf[i], x1 = wbuf[i + 1];
            const unsigned ph = bfpair(x0, x1);
            const float h0 = __uint_as_float(ph << 16);
            const float h1 = __uint_as_float(ph & 0xFFFF0000u);
            const unsigned pl = bfpair(x0 - h0, x1 - h1);
            whl[cur][i] = (ull)ph | ((ull)pl << 32);
        }

        // Issue next B chunk + prefetch next x while this chunk computes.
        {
            const unsigned* src = gb + cn * CHUNK_WORDS + tid * 4;
            #pragma unroll
            for (int r = 0; r < 4; r++)
                cpasync16(&bbuf[nxt][tid * 4 + r * 512], src + r * 512);
            asm volatile("cp.async.commit_group;" ::: "memory");
            const int g0 = t0 + lo + cn * KC - P;
            const int ga = g0 + tid, gv = g0 + 128 + tid;
            xr0 = (ga >= 0 && ga < T) ? __ldg(xb + ga) : 0.0f;
            xr1 = (tid < 66 && gv >= 0 && gv < T) ? __ldg(xb + gv) : 0.0f;
        }
        asm volatile("cp.async.wait_group 1;" ::: "memory");
        __syncthreads();

        const uint4* bs = (const uint4*)bbuf[cur];
        #pragma unroll
        for (int kk = 0; kk < 4; kk++) {
            // B fragments: conflict-free LDS.128 (lane stride 16B).
            const uint4 bh0 = bs[(kk * 2 + 0) * 32 + lane];
            const uint4 bh1 = bs[(kk * 2 + 1) * 32 + lane];
            const uint4 bl0 = bs[256 + (kk * 2 + 0) * 32 + lane];
            const uint4 bl1 = bs[256 + (kk * 2 + 1) * 32 + lane];
            #pragma unroll
            for (int mt = 0; mt < 2; mt++) {
                const int ai = abase + mt * 16 + kk * 16;
                const ull pa = whl[cur][ai];
                const ull pb = whl[cur][ai + 8];
                const ull pc = whl[cur][ai + 16];
                const unsigned ha = (unsigned)pa, la = (unsigned)(pa >> 32);
                const unsigned hb = (unsigned)pb, lb = (unsigned)(pb >> 32);
                const unsigned hc = (unsigned)pc, lc = (unsigned)(pc >> 32);
                // xh*fh
                mma_bf16(acc[mt][0], ha, hb, hb, hc, bh0.x, bh1.x);
                mma_bf16(acc[mt][1], ha, hb, hb, hc, bh0.y, bh1.y);
                mma_bf16(acc[mt][2], ha, hb, hb, hc, bh0.z, bh1.z);
                mma_bf16(acc[mt][3], ha, hb, hb, hc, bh0.w, bh1.w);
                // xl*fh
                mma_bf16(acc[mt][0], la, lb, lb, lc, bh0.x, bh1.x);
                mma_bf16(acc[mt][1], la, lb, lb, lc, bh0.y, bh1.y);
                mma_bf16(acc[mt][2], la, lb, lb, lc, bh0.z, bh1.z);
                mma_bf16(acc[mt][3], la, lb, lb, lc, bh0.w, bh1.w);
                // xh*fl
                mma_bf16(acc[mt][0], ha, hb, hb, hc, bl0.x, bl1.x);
                mma_bf16(acc[mt][1], ha, hb, hb, hc, bl0.y, bl1.y);
                mma_bf16(acc[mt][2], ha, hb, hb, hc, bl0.z, bl1.z);
                mma_bf16(acc[mt][3], ha, hb, hb, hc, bl0.w, bl1.w);
            }
        }
    }

    // Epilogue: acc cols (2(lane&3), +1) = (re, im) of filter q = c*4 + (lane&3);
    // rows m0 + mt*16 (+8 for regs 2,3).
    const int m0 = t0 + wix * 32 + (lane >> 2);
    #pragma unroll
    for (int mt = 0; mt < 2; mt++)
        #pragma unroll
        for (int c = 0; c < 4; c++) {
            const int q = c * 4 + (lane & 3);
            float* op = out + ((size_t)b * KFILT + j * QSTEP + q) * T + m0 + mt * 16;
            op[0] = sqrtf(acc[mt][c][0] * acc[mt][c][0] + acc[mt][c][1] * acc[mt][c][1]);
            op[8] = sqrtf(acc[mt][c][2] * acc[mt][c][2] + acc[mt][c][3] * acc[mt][c][3]);
        }
}

extern "C" void kernel_launch(void* const* d_in, const int* in_sizes, int n_in,
                              void* d_out, int out_size)
{
    const float* x  = (const float*)d_in[0];
    const float* fr = (const float*)d_in[1];
    const float* fi = (const float*)d_in[2];
    float* out = (float*)d_out;

    const int T = in_sizes[0] / NBATCH;      // 32768
    const int L = in_sizes[1] / KFILT;       // ~47071 (odd)
    const int P = L / 2;

    prep_bank<<<dim3(768, NOCT), 256>>>(fr, fi, L, P);
    scat_mma_kernel<<<dim3(T / MT_M, NOCT, NBATCH), 128>>>(x, out, T, L, P);
}

// round 12
// speedup vs baseline: 1.4329x; 1.4329x over previous
#include <cuda_runtime.h>
#include <math.h>

// ScatTransform1D via implicit GEMM on fallback HMMA (mma.sync.m16n8k16.f16),
// x split into fp16 hi/lo (exact), f single fp16 -> 2 MMA products:
//   y = xh*f + xl*f     (error = f quantization only, ~2^-12/sqrt(3) global)
//
// Round 11: round-8 skeleton (direct LDG for B), KC=128 taps per barrier trio
// (two 64-tap sub-chunks), halved bank (single f copy).

#define KFILT 192
#define QSTEP 16
#define NBATCH 2
#define NOCT 12
#define MT_M 128
#define KC 64
#define CHUNK_WORDS 1024           // (4 kk)(2 rr)(32 lane)(4 c) words, single f
#define MAX_CHUNKS_TOTAL 1600      // sum over octaves of even-rounded nc_j

typedef unsigned long long ull;

__device__ __align__(16) unsigned g_bank[MAX_CHUNKS_TOTAL * CHUNK_WORDS]; // 6.5MB

static __device__ __forceinline__ unsigned fpair(float lo, float hi) {
    unsigned r;   // lower 16 bits <- lo (tap k), upper <- hi (tap k+1)
    asm("cvt.rn.f16x2.f32 %0, %1, %2;" : "=r"(r) : "f"(hi), "f"(lo));
    return r;
}
static __device__ __forceinline__ float2 unpk16(unsigned p) {
    float a, b;
    asm("{ .reg .b16 l, h; mov.b32 {l, h}, %2; cvt.f32.f16 %0, l; cvt.f32.f16 %1, h; }"
        : "=f"(a), "=f"(b) : "r"(p));
    return make_float2(a, b);
}

// Octave support params; MUST be identical in prep + main kernels.
// nc rounded up to EVEN (extra chunk covers exactly-zero padded filter taps).
static __device__ __forceinline__ int oct_params(int j, int P, int* lo, int* nc) {
    int off = 0;
    for (int jj = 0; jj <= j; jj++) {
        int M = (int)ceil(6.0 * exp2((double)jj + 0.9375)) + 2;  // max-q support
        if (M > P) M = P;
        int c = (2 * M + KC) / KC;          // ceil((2M+1)/64)
        c = (c + 1) & ~1;                   // round up to even
        if (jj < j) off += c;
        else { *lo = P - M; *nc = c; }
    }
    return off * CHUNK_WORDS;
}

// ---------------------------------------------------------------- prep kernel
// word index = (((kk*2 + rr)*32 + lane)*4 + c)
//   n = c*8 + (lane>>2); tap k = kk*16 + rr*8 + (lane&3)*2; d = lo + ci*64 + k
// Each word = packed fp16 pair (f[d], f[d+1]).
__global__ void prep_bank(const float* __restrict__ fr, const float* __restrict__ fi,
                          int L, int P)
{
    __shared__ float fsm[32][66];
    const int j = blockIdx.y;
    int lo, nc;
    const int off = oct_params(j, P, &lo, &nc);
    const int ci = blockIdx.x;
    if (ci >= nc) return;
    const int d0 = lo + ci * KC;

    // Stage: thread (n = tid>>3) reads 8 consecutive taps at kb = (tid&7)*8.
    {
        const int n  = threadIdx.x >> 3;
        const int kb = (threadIdx.x & 7) * 8;
        const float* src = ((n & 1) ? fi : fr) + (size_t)(j * QSTEP + (n >> 1)) * L;
        #pragma unroll
        for (int u = 0; u < 8; u++) {
            const int d = d0 + kb + u;
            fsm[n][kb + u] = (d >= 0 && d < L) ? __ldg(src + d) : 0.0f;
        }
    }
    __syncthreads();

    unsigned* dst = g_bank + off + ci * CHUNK_WORDS;
    for (int wd = threadIdx.x; wd < CHUNK_WORDS; wd += blockDim.x) {
        const int c    = wd & 3;
        const int lane = (wd >> 2) & 31;
        const int rr   = (wd >> 7) & 1;
        const int kk   = (wd >> 8) & 3;
        const int n    = c * 8 + (lane >> 2);
        const int k    = kk * 16 + rr * 8 + (lane & 3) * 2;
        dst[wd] = fpair(fsm[n][k], fsm[n][k + 1]);
    }
}

// ---------------------------------------------------------------- main kernel
static __device__ __forceinline__ void mma_f16(float c[4],
                                               unsigned a0, unsigned a1,
                                               unsigned a2, unsigned a3,
                                               unsigned b0, unsigned b1)
{
    asm volatile(
        "mma.sync.aligned.m16n8k16.row.col.f32.f16.f16.f32 "
        "{%0,%1,%2,%3}, {%4,%5,%6,%7}, {%8,%9}, {%0,%1,%2,%3};"
        : "+f"(c[0]), "+f"(c[1]), "+f"(c[2]), "+f"(c[3])
        : "r"(a0), "r"(a1), "r"(a2), "r"(a3), "r"(b0), "r"(b1));
}

__global__ __launch_bounds__(128)
void scat_mma_kernel(const float* __restrict__ x, float* __restrict__ out,
                     int T, int L, int P)
{
    __shared__ float wbuf[264];
    __shared__ ull   whl[256];    // low 32b: fp16 hi-pair, high 32b: lo-pair

    const int tid  = threadIdx.x;
    const int wix  = tid >> 5;
    const int lane = tid & 31;
    const int t0   = blockIdx.x * MT_M;
    const int j    = (NOCT - 1) - blockIdx.y;    // heavy octaves first
    const int b    = blockIdx.z;

    int lo, nc;
    const int off = oct_params(j, P, &lo, &nc);
    const int nc2 = nc >> 1;                     // nc is even
    const float* xb = x + (size_t)b * T;
    const unsigned* gb = g_bank + off;

    float acc[2][4][4];
    #pragma unroll
    for (int mt = 0; mt < 2; mt++)
        #pragma unroll
        for (int c = 0; c < 4; c++)
            #pragma unroll
            for (int r = 0; r < 4; r++) acc[mt][c][r] = 0.0f;

    // A-fragment base: m + k with m = wix*32 + (lane>>2), k = 2*(lane&3).
    // Toeplitz: (+8 row) and (+8 col) fragments coincide.
    const int abase = wix * 32 + (lane >> 2) + (lane & 3) * 2;

    for (int ci2 = 0; ci2 < nc2; ci2++) {
        __syncthreads();                         // prev MMA reads of whl done
        // Window covers 256 taps span: [t0 + lo + ci2*128 - P, +258)
        const int g0 = t0 + lo + ci2 * 128 - P;
        for (int i = tid; i < 258; i += 128) {
            const int g = g0 + i;
            wbuf[i] = (g >= 0 && g < T) ? __ldg(xb + g) : 0.0f;
        }
        __syncthreads();
        // Convert -> packed fp16 (hi, lo) pairs; x split is exact to 2^-24.
        #pragma unroll
        for (int i = tid; i < 256; i += 128) {
            const float x0 = wbuf[i], x1 = wbuf[i + 1];
            const unsigned ph = fpair(x0, x1);
            const float2 hf = unpk16(ph);
            const unsigned pl = fpair(x0 - hf.x, x1 - hf.y);
            whl[i] = (ull)ph | ((ull)pl << 32);
        }
        __syncthreads();

        #pragma unroll
        for (int kc2 = 0; kc2 < 2; kc2++) {
            const uint4* bs = (const uint4*)(gb + (ci2 * 2 + kc2) * CHUNK_WORDS);
            #pragma unroll
            for (int kk = 0; kk < 4; kk++) {
                // B fragments: 2 coalesced LDG.128 (x/y/z/w = n-tiles 0..3).
                const uint4 b0 = __ldg(bs + (kk * 2 + 0) * 32 + lane);
                const uint4 b1 = __ldg(bs + (kk * 2 + 1) * 32 + lane);
                #pragma unroll
                for (int mt = 0; mt < 2; mt++) {
                    const int ai = abase + mt * 16 + kc2 * 64 + kk * 16;
                    const ull pa = whl[ai];
                    const ull pb = whl[ai + 8];
                    const ull pc = whl[ai + 16];
                    const unsigned ha = (unsigned)pa, la = (unsigned)(pa >> 32);
                    const unsigned hb = (unsigned)pb, lb = (unsigned)(pb >> 32);
                    const unsigned hc = (unsigned)pc, lc = (unsigned)(pc >> 32);
                    // xh * f
                    mma_f16(acc[mt][0], ha, hb, hb, hc, b0.x, b1.x);
                    mma_f16(acc[mt][1], ha, hb, hb, hc, b0.y, b1.y);
                    mma_f16(acc[mt][2], ha, hb, hb, hc, b0.z, b1.z);
                    mma_f16(acc[mt][3], ha, hb, hb, hc, b0.w, b1.w);
                    // xl * f
                    mma_f16(acc[mt][0], la, lb, lb, lc, b0.x, b1.x);
                    mma_f16(acc[mt][1], la, lb, lb, lc, b0.y, b1.y);
                    mma_f16(acc[mt][2], la, lb, lb, lc, b0.z, b1.z);
                    mma_f16(acc[mt][3], la, lb, lb, lc, b0.w, b1.w);
                }
            }
        }
    }

    // Epilogue: acc cols (2(lane&3), +1) = (re, im) of filter q = c*4 + (lane&3);
    // rows m0 + mt*16 (+8 for regs 2,3).
    const int m0 = t0 + wix * 32 + (lane >> 2);
    #pragma unroll
    for (int mt = 0; mt < 2; mt++)
        #pragma unroll
        for (int c = 0; c < 4; c++) {
            const int q = c * 4 + (lane & 3);
            float* op = out + ((size_t)b * KFILT + j * QSTEP + q) * T + m0 + mt * 16;
            op[0] = sqrtf(acc[mt][c][0] * acc[mt][c][0] + acc[mt][c][1] * acc[mt][c][1]);
            op[8] = sqrtf(acc[mt][c][2] * acc[mt][c][2] + acc[mt][c][3] * acc[mt][c][3]);
        }
}

extern "C" void kernel_launch(void* const* d_in, const int* in_sizes, int n_in,
                              void* d_out, int out_size)
{
    const float* x  = (const float*)d_in[0];
    const float* fr = (const float*)d_in[1];
    const float* fi = (const float*)d_in[2];
    float* out = (float*)d_out;

    const int T = in_sizes[0] / NBATCH;      // 32768
    const int L = in_sizes[1] / KFILT;       // ~47071 (odd)
    const int P = L / 2;

    prep_bank<<<dim3(768, NOCT), 256>>>(fr, fi, L, P);
    scat_mma_kernel<<<dim3(T / MT_M, NOCT, NBATCH), 128>>>(x, out, T, L, P);
}

// round 16
// speedup vs baseline: 1.5860x; 1.1069x over previous
#include <cuda_runtime.h>
#include <math.h>

// ScatTransform1D via implicit GEMM on fallback HMMA (mma.sync.m16n8k16.f16),
// x split into fp16 hi/lo (exact), f single fp16 -> 2 MMA products:
//   y = xh*f + xl*f     (error = f quantization only, ~2^-12/sqrt(3) global)
//
// Round 13: MT_M=256 (4 m-tiles/warp) halves B+window cost per HMMA;
// Toeplitz fragment sharing: frag index depends only on s=mt+kk -> 15 LDS.64
// per 64-tap chunk (rolling 9-reg window); whl double-buffered, built straight
// from gmem -> 1 syncthreads per 128 taps.

#define KFILT 192
#define QSTEP 16
#define NBATCH 2
#define NOCT 12
#define MT_M 256
#define KC 64
#define CHUNK_WORDS 1024           // (4 kk)(2 rr)(32 lane)(4 c) words, single f
#define MAX_CHUNKS_TOTAL 1600      // sum over octaves of even-rounded nc_j

typedef unsigned long long ull;

__device__ __align__(16) unsigned g_bank[MAX_CHUNKS_TOTAL * CHUNK_WORDS]; // 6.5MB

static __device__ __forceinline__ unsigned fpair(float lo, float hi) {
    unsigned r;   // lower 16 bits <- lo (tap k), upper <- hi (tap k+1)
    asm("cvt.rn.f16x2.f32 %0, %1, %2;" : "=r"(r) : "f"(hi), "f"(lo));
    return r;
}
static __device__ __forceinline__ float2 unpk16(unsigned p) {
    float a, b;
    asm("{ .reg .b16 l, h; mov.b32 {l, h}, %2; cvt.f32.f16 %0, l; cvt.f32.f16 %1, h; }"
        : "=f"(a), "=f"(b) : "r"(p));
    return make_float2(a, b);
}

// Octave support params; MUST be identical in prep + main kernels.
// nc rounded up to EVEN (extra chunk covers exactly-zero padded filter taps).
static __device__ __forceinline__ int oct_params(int j, int P, int* lo, int* nc) {
    int off = 0;
    for (int jj = 0; jj <= j; jj++) {
        int M = (int)ceil(6.0 * exp2((double)jj + 0.9375)) + 2;  // max-q support
        if (M > P) M = P;
        int c = (2 * M + KC) / KC;          // ceil((2M+1)/64)
        c = (c + 1) & ~1;                   // round up to even
        if (jj < j) off += c;
        else { *lo = P - M; *nc = c; }
    }
    return off * CHUNK_WORDS;
}

// ---------------------------------------------------------------- prep kernel
// word index = (((kk*2 + rr)*32 + lane)*4 + c)
//   n = c*8 + (lane>>2); tap k = kk*16 + rr*8 + (lane&3)*2; d = lo + ci*64 + k
// Each word = packed fp16 pair (f[d], f[d+1]).
__global__ void prep_bank(const float* __restrict__ fr, const float* __restrict__ fi,
                          int L, int P)
{
    __shared__ float fsm[32][66];
    const int j = blockIdx.y;
    int lo, nc;
    const int off = oct_params(j, P, &lo, &nc);
    const int ci = blockIdx.x;
    if (ci >= nc) return;
    const int d0 = lo + ci * KC;

    // Stage: thread (n = tid>>3) reads 8 consecutive taps at kb = (tid&7)*8.
    {
        const int n  = threadIdx.x >> 3;
        const int kb = (threadIdx.x & 7) * 8;
        const float* src = ((n & 1) ? fi : fr) + (size_t)(j * QSTEP + (n >> 1)) * L;
        #pragma unroll
        for (int u = 0; u < 8; u++) {
            const int d = d0 + kb + u;
            fsm[n][kb + u] = (d >= 0 && d < L) ? __ldg(src + d) : 0.0f;
        }
    }
    __syncthreads();

    unsigned* dst = g_bank + off + ci * CHUNK_WORDS;
    for (int wd = threadIdx.x; wd < CHUNK_WORDS; wd += blockDim.x) {
        const int c    = wd & 3;
        const int lane = (wd >> 2) & 31;
        const int rr   = (wd >> 7) & 1;
        const int kk   = (wd >> 8) & 3;
        const int n    = c * 8 + (lane >> 2);
        const int k    = kk * 16 + rr * 8 + (lane & 3) * 2;
        dst[wd] = fpair(fsm[n][k], fsm[n][k + 1]);
    }
}

// ---------------------------------------------------------------- main kernel
static __device__ __forceinline__ void mma_f16(float c[4],
                                               unsigned a0, unsigned a1,
                                               unsigned a2, unsigned a3,
                                               unsigned b0, unsigned b1)
{
    asm volatile(
        "mma.sync.aligned.m16n8k16.row.col.f32.f16.f16.f32 "
        "{%0,%1,%2,%3}, {%4,%5,%6,%7}, {%8,%9}, {%0,%1,%2,%3};"
        : "+f"(c[0]), "+f"(c[1]), "+f"(c[2]), "+f"(c[3])
        : "r"(a0), "r"(a1), "r"(a2), "r"(a3), "r"(b0), "r"(b1));
}

__global__ __launch_bounds__(128)
void scat_mma_kernel(const float* __restrict__ x, float* __restrict__ out,
                     int T, int L, int P)
{
    __shared__ ull whl[2][384];   // low 32b: fp16 hi-pair, high 32b: lo-pair

    const int tid  = threadIdx.x;
    const int wix  = tid >> 5;
    const int lane = tid & 31;
    const int t0   = blockIdx.x * MT_M;
    const int j    = (NOCT - 1) - blockIdx.y;    // heavy octaves first
    const int b    = blockIdx.z;

    int lo, nc;
    const int off = oct_params(j, P, &lo, &nc);
    const int nc2 = nc >> 1;                     // nc is even
    const float* xb = x + (size_t)b * T;
    const unsigned* gb = g_bank + off;

    float acc[4][4][4];
    #pragma unroll
    for (int mt = 0; mt < 4; mt++)
        #pragma unroll
        for (int c = 0; c < 4; c++)
            #pragma unroll
            for (int r = 0; r < 4; r++) acc[mt][c][r] = 0.0f;

    // A-fragment base: m + k with m = wix*64 + (lane>>2), k = 2*(lane&3).
    // Toeplitz: fragment set depends only on s = mt + kk.
    const int abase = wix * 64 + (lane >> 2) + (lane & 3) * 2;

    for (int ci2 = 0; ci2 < nc2; ci2++) {
        const int buf = ci2 & 1;
        // Build packed fp16 (hi, lo) window straight from gmem (x is L2-hot).
        // whl[buf][i] packs taps (i, i+1) of span starting at g0.
        const int g0 = t0 + lo + ci2 * 128 - P;
        #pragma unroll
        for (int u = 0; u < 3; u++) {
            const int i = tid + u * 128;
            const int g = g0 + i;
            const float x0 = (g >= 0 && g < T)         ? __ldg(xb + g)     : 0.0f;
            const float x1 = (g + 1 >= 0 && g + 1 < T) ? __ldg(xb + g + 1) : 0.0f;
            const unsigned ph = fpair(x0, x1);
            const float2 hf = unpk16(ph);
            const unsigned pl = fpair(x0 - hf.x, x1 - hf.y);
            whl[buf][i] = (ull)ph | ((ull)pl << 32);
        }
        __syncthreads();   // writes visible; also fences prior-iter reads of buf

        #pragma unroll
        for (int kc2 = 0; kc2 < 2; kc2++) {
            const int wb = abase + kc2 * 64;
            // Rolling 9-fragment window over s = mt + kk.
            ull w[9];
            #pragma unroll
            for (int u = 0; u < 9; u++) w[u] = whl[buf][wb + 8 * u];

            const uint4* bs = (const uint4*)(gb + (ci2 * 2 + kc2) * CHUNK_WORDS);
            #pragma unroll
            for (int kk = 0; kk < 4; kk++) {
                const uint4 b0 = __ldg(bs + (kk * 2 + 0) * 32 + lane);
                const uint4 b1 = __ldg(bs + (kk * 2 + 1) * 32 + lane);
                #pragma unroll
                for (int mt = 0; mt < 4; mt++) {
                    const ull pa = w[2 * mt];
                    const ull pb = w[2 * mt + 1];
                    const ull pc = w[2 * mt + 2];
                    const unsigned ha = (unsigned)pa, la = (unsigned)(pa >> 32);
                    const unsigned hb = (unsigned)pb, lb = (unsigned)(pb >> 32);
                    const unsigned hc = (unsigned)pc, lc = (unsigned)(pc >> 32);
                    // xh * f
                    mma_f16(acc[mt][0], ha, hb, hb, hc, b0.x, b1.x);
                    mma_f16(acc[mt][1], ha, hb, hb, hc, b0.y, b1.y);
                    mma_f16(acc[mt][2], ha, hb, hb, hc, b0.z, b1.z);
                    mma_f16(acc[mt][3], ha, hb, hb, hc, b0.w, b1.w);
                    // xl * f
                    mma_f16(acc[mt][0], la, lb, lb, lc, b0.x, b1.x);
                    mma_f16(acc[mt][1], la, lb, lb, lc, b0.y, b1.y);
                    mma_f16(acc[mt][2], la, lb, lb, lc, b0.z, b1.z);
                    mma_f16(acc[mt][3], la, lb, lb, lc, b0.w, b1.w);
                }
                if (kk < 3) {
                    #pragma unroll
                    for (int u = 0; u < 7; u++) w[u] = w[u + 2];
                    w[7] = whl[buf][wb + 8 * (9 + 2 * kk)];
                    w[8] = whl[buf][wb + 8 * (10 + 2 * kk)];
                }
            }
        }
    }

    // Epilogue: acc cols (2(lane&3), +1) = (re, im) of filter q = c*4 + (lane&3);
    // rows m0 + mt*16 (+8 for regs 2,3).
    const int m0 = t0 + wix * 64 + (lane >> 2);
    #pragma unroll
    for (int mt = 0; mt < 4; mt++)
        #pragma unroll
        for (int c = 0; c < 4; c++) {
            const int q = c * 4 + (lane & 3);
            float* op = out + ((size_t)b * KFILT + j * QSTEP + q) * T + m0 + mt * 16;
            op[0] = sqrtf(acc[mt][c][0] * acc[mt][c][0] + acc[mt][c][1] * acc[mt][c][1]);
            op[8] = sqrtf(acc[mt][c][2] * acc[mt][c][2] + acc[mt][c][3] * acc[mt][c][3]);
        }
}

extern "C" void kernel_launch(void* const* d_in, const int* in_sizes, int n_in,
                              void* d_out, int out_size)
{
    const float* x  = (const float*)d_in[0];
    const float* fr = (const float*)d_in[1];
    const float* fi = (const float*)d_in[2];
    float* out = (float*)d_out;

    const int T = in_sizes[0] / NBATCH;      // 32768
    const int L = in_sizes[1] / KFILT;       // ~47071 (odd)
    const int P = L / 2;

    prep_bank<<<dim3(736, NOCT), 256>>>(fr, fi, L, P);
    scat_mma_kernel<<<dim3(T / MT_M, NOCT, NBATCH), 128>>>(x, out, T, L, P);
}

// round 17
// speedup vs baseline: 1.6079x; 1.0137x over previous
#include <cuda_runtime.h>
#include <math.h>

// ScatTransform1D via implicit GEMM on fallback HMMA (mma.sync.m16n8k16.f16),
// x split into fp16 hi/lo (exact), f single fp16 -> 2 MMA products:
//   y = xh*f + xl*f     (error = f quantization only, ~2^-12/sqrt(3) global)
//
// Round 17: MT_M=256 kept, but BLOCK=256 (8 warps x 2 m-tiles) -> regs ~90,
// 3 blocks/SM = 24 warps (occ 50%) for latency hiding; Toeplitz rolling
// 11-fragment window; explicit B prefetch one kk ahead; 1 sync per 128 taps.

#define KFILT 192
#define QSTEP 16
#define NBATCH 2
#define NOCT 12
#define MT_M 256
#define BLOCK 256
#define KC 64
#define CHUNK_WORDS 1024           // (4 kk)(2 rr)(32 lane)(4 c) words, single f
#define MAX_CHUNKS_TOTAL 1600      // sum over octaves of even-rounded nc_j

typedef unsigned long long ull;

__device__ __align__(16) unsigned g_bank[MAX_CHUNKS_TOTAL * CHUNK_WORDS]; // 6.5MB

static __device__ __forceinline__ unsigned fpair(float lo, float hi) {
    unsigned r;   // lower 16 bits <- lo (tap k), upper <- hi (tap k+1)
    asm("cvt.rn.f16x2.f32 %0, %1, %2;" : "=r"(r) : "f"(hi), "f"(lo));
    return r;
}
static __device__ __forceinline__ float2 unpk16(unsigned p) {
    float a, b;
    asm("{ .reg .b16 l, h; mov.b32 {l, h}, %2; cvt.f32.f16 %0, l; cvt.f32.f16 %1, h; }"
        : "=f"(a), "=f"(b) : "r"(p));
    return make_float2(a, b);
}

// Octave support params; MUST be identical in prep + main kernels.
// nc rounded up to EVEN (extra chunk covers exactly-zero padded filter taps).
static __device__ __forceinline__ int oct_params(int j, int P, int* lo, int* nc) {
    int off = 0;
    for (int jj = 0; jj <= j; jj++) {
        int M = (int)ceil(6.0 * exp2((double)jj + 0.9375)) + 2;  // max-q support
        if (M > P) M = P;
        int c = (2 * M + KC) / KC;          // ceil((2M+1)/64)
        c = (c + 1) & ~1;                   // round up to even
        if (jj < j) off += c;
        else { *lo = P - M; *nc = c; }
    }
    return off * CHUNK_WORDS;
}

// ---------------------------------------------------------------- prep kernel
// word index = (((kk*2 + rr)*32 + lane)*4 + c)
//   n = c*8 + (lane>>2); tap k = kk*16 + rr*8 + (lane&3)*2; d = lo + ci*64 + k
// Each word = packed fp16 pair (f[d], f[d+1]).
__global__ void prep_bank(const float* __restrict__ fr, const float* __restrict__ fi,
                          int L, int P)
{
    __shared__ float fsm[32][66];
    const int j = blockIdx.y;
    int lo, nc;
    const int off = oct_params(j, P, &lo, &nc);
    const int ci = blockIdx.x;
    if (ci >= nc) return;
    const int d0 = lo + ci * KC;

    // Stage: thread (n = tid>>3) reads 8 consecutive taps at kb = (tid&7)*8.
    {
        const int n  = threadIdx.x >> 3;
        const int kb = (threadIdx.x & 7) * 8;
        const float* src = ((n & 1) ? fi : fr) + (size_t)(j * QSTEP + (n >> 1)) * L;
        #pragma unroll
        for (int u = 0; u < 8; u++) {
            const int d = d0 + kb + u;
            fsm[n][kb + u] = (d >= 0 && d < L) ? __ldg(src + d) : 0.0f;
        }
    }
    __syncthreads();

    unsigned* dst = g_bank + off + ci * CHUNK_WORDS;
    for (int wd = threadIdx.x; wd < CHUNK_WORDS; wd += blockDim.x) {
        const int c    = wd & 3;
        const int lane = (wd >> 2) & 31;
        const int rr   = (wd >> 7) & 1;
        const int kk   = (wd >> 8) & 3;
        const int n    = c * 8 + (lane >> 2);
        const int k    = kk * 16 + rr * 8 + (lane & 3) * 2;
        dst[wd] = fpair(fsm[n][k], fsm[n][k + 1]);
    }
}

// ---------------------------------------------------------------- main kernel
static __device__ __forceinline__ void mma_f16(float c[4],
                                               unsigned a0, unsigned a1,
                                               unsigned a2, unsigned a3,
                                               unsigned b0, unsigned b1)
{
    asm volatile(
        "mma.sync.aligned.m16n8k16.row.col.f32.f16.f16.f32 "
        "{%0,%1,%2,%3}, {%4,%5,%6,%7}, {%8,%9}, {%0,%1,%2,%3};"
        : "+f"(c[0]), "+f"(c[1]), "+f"(c[2]), "+f"(c[3])
        : "r"(a0), "r"(a1), "r"(a2), "r"(a3), "r"(b0), "r"(b1));
}

__global__ __launch_bounds__(BLOCK)
void scat_mma_kernel(const float* __restrict__ x, float* __restrict__ out,
                     int T, int L, int P)
{
    __shared__ ull whl[2][384];   // low 32b: fp16 hi-pair, high 32b: lo-pair

    const int tid  = threadIdx.x;
    const int wix  = tid >> 5;            // 0..7
    const int lane = tid & 31;
    const int t0   = blockIdx.x * MT_M;
    const int j    = (NOCT - 1) - blockIdx.y;    // heavy octaves first
    const int b    = blockIdx.z;

    int lo, nc;
    const int off = oct_params(j, P, &lo, &nc);
    const int nc2 = nc >> 1;                     // nc is even
    const float* xb = x + (size_t)b * T;
    const unsigned* gb = g_bank + off;

    float acc[2][4][4];
    #pragma unroll
    for (int mt = 0; mt < 2; mt++)
        #pragma unroll
        for (int c = 0; c < 4; c++)
            #pragma unroll
            for (int r = 0; r < 4; r++) acc[mt][c][r] = 0.0f;

    // A-fragment base: m + k with m = wix*32 + (lane>>2), k = 2*(lane&3).
    // Toeplitz: fragments depend only on s = mt + kk in [0,4] ->
    // distinct values whl[ab + 8r], r in [0,10]: 11-reg rolling window.
    const int abase = wix * 32 + (lane >> 2) + (lane & 3) * 2;

    for (int ci2 = 0; ci2 < nc2; ci2++) {
        const int buf = ci2 & 1;
        // Build packed fp16 (hi, lo) window straight from gmem (x is L2-hot).
        const int g0 = t0 + lo + ci2 * 128 - P;
        #pragma unroll
        for (int u = 0; u < 2; u++) {
            const int i = tid + u * 256;
            if (i < 384) {
                const int g = g0 + i;
                const float x0 = (g >= 0 && g < T)     ? __ldg(xb + g)     : 0.0f;
                const float x1 = (g + 1 >= 0 && g + 1 < T) ? __ldg(xb + g + 1) : 0.0f;
                const unsigned ph = fpair(x0, x1);
                const float2 hf = unpk16(ph);
                const unsigned pl = fpair(x0 - hf.x, x1 - hf.y);
                whl[buf][i] = (ull)ph | ((ull)pl << 32);
            }
        }
        __syncthreads();   // writes visible; also fences older reads of this buf

        #pragma unroll
        for (int kc2 = 0; kc2 < 2; kc2++) {
            const int wb = abase + kc2 * 64;
            ull w[11];
            #pragma unroll
            for (int u = 0; u < 11; u++) w[u] = whl[buf][wb + 8 * u];

            const uint4* bs = (const uint4*)(gb + (ci2 * 2 + kc2) * CHUNK_WORDS);
            // B prefetch one kk ahead.
            uint4 b0 = __ldg(bs + 0 * 32 + lane);
            uint4 b1 = __ldg(bs + 1 * 32 + lane);
            #pragma unroll
            for (int kk = 0; kk < 4; kk++) {
                uint4 nb0, nb1;
                if (kk < 3) {
                    nb0 = __ldg(bs + ((kk + 1) * 2 + 0) * 32 + lane);
                    nb1 = __ldg(bs + ((kk + 1) * 2 + 1) * 32 + lane);
                }
                #pragma unroll
                for (int mt = 0; mt < 2; mt++) {
                    const int s = 2 * (mt + kk);
                    const ull pa = w[s];
                    const ull pb = w[s + 1];
                    const ull pc = w[s + 2];
                    const unsigned ha = (unsigned)pa, la = (unsigned)(pa >> 32);
                    const unsigned hb = (unsigned)pb, lb = (unsigned)(pb >> 32);
                    const unsigned hc = (unsigned)pc, lc = (unsigned)(pc >> 32);
                    // xh * f
                    mma_f16(acc[mt][0], ha, hb, hb, hc, b0.x, b1.x);
                    mma_f16(acc[mt][1], ha, hb, hb, hc, b0.y, b1.y);
                    mma_f16(acc[mt][2], ha, hb, hb, hc, b0.z, b1.z);
                    mma_f16(acc[mt][3], ha, hb, hb, hc, b0.w, b1.w);
                    // xl * f
                    mma_f16(acc[mt][0], la, lb, lb, lc, b0.x, b1.x);
                    mma_f16(acc[mt][1], la, lb, lb, lc, b0.y, b1.y);
                    mma_f16(acc[mt][2], la, lb, lb, lc, b0.z, b1.z);
                    mma_f16(acc[mt][3], la, lb, lb, lc, b0.w, b1.w);
                }
                if (kk < 3) { b0 = nb0; b1 = nb1; }
            }
        }
    }

    // Epilogue: acc cols (2(lane&3), +1) = (re, im) of filter q = c*4 + (lane&3);
    // rows m0 + mt*16 (+8 for regs 2,3).
    const int m0 = t0 + wix * 32 + (lane >> 2);
    #pragma unroll
    for (int mt = 0; mt < 2; mt++)
        #pragma unroll
        for (int c = 0; c < 4; c++) {
            const int q = c * 4 + (lane & 3);
            float* op = out + ((size_t)b * KFILT + j * QSTEP + q) * T + m0 + mt * 16;
            op[0] = sqrtf(acc[mt][c][0] * acc[mt][c][0] + acc[mt][c][1] * acc[mt][c][1]);
            op[8] = sqrtf(acc[mt][c][2] * acc[mt][c][2] + acc[mt][c][3] * acc[mt][c][3]);
        }
}

extern "C" void kernel_launch(void* const* d_in, const int* in_sizes, int n_in,
                              void* d_out, int out_size)
{
    const float* x  = (const float*)d_in[0];
    const float* fr = (const float*)d_in[1];
    const float* fi = (const float*)d_in[2];
    float* out = (float*)d_out;

    const int T = in_sizes[0] / NBATCH;      // 32768
    const int L = in_sizes[1] / KFILT;       // ~47071 (odd)
    const int P = L / 2;

    prep_bank<<<dim3(736, NOCT), 256>>>(fr, fi, L, P);
    scat_mma_kernel<<<dim3(T / MT_M, NOCT, NBATCH), BLOCK>>>(x, out, T, L, P);
}